// round 15
// baseline (speedup 1.0000x reference)
#include <cuda_runtime.h>
#include <cuda_fp16.h>
#include <cstdint>

#define NUM_E 16
#define D_IN  2048
#define D_OUT 8192
#define T_TOK 8192

// GEMM: CTA 128x128, BK=64, 8 warps 2(M)x4(N), warp 64x32, single-term fp16,
// fully-async 3-stage cp.async pipeline (A and B both pre-converted to fp16).
#define BM 128
#define BN 128
#define BK 64
#define NCHUNK (D_IN / BK)   // 32
#define THREADS 256
#define NSTAGE 3

#define REG_SZ  4096
#define A_T     0                     // 16KB (4 k16-halves)
#define B_T     16384                 // 16KB
#define STAGE_B 32768
#define SMEM_BYTES (NSTAGE * STAGE_B) // 98304

// Pre-converted fp16 operands (device-global scratch).
__device__ __half g_Ah[(size_t)T_TOK * D_IN];                  // 32MB
__device__ __half g_Bh[(size_t)NUM_E * D_OUT * D_IN];          // 512MB

__device__ __forceinline__ uint32_t swz(uint32_t a) {
    return a ^ ((a & 128u) >> 3);
}

__device__ __forceinline__ uint32_t smem_u32_of(const void* p) {
    uint32_t a;
    asm("{ .reg .u64 t; cvta.to.shared.u64 t, %1; cvt.u32.u64 %0, t; }" : "=r"(a) : "l"(p));
    return a;
}

__device__ __forceinline__ uint32_t pack2h(__half a, __half b) {
    __half2 t = __halves2half2(a, b);
    return *reinterpret_cast<uint32_t*>(&t);
}

__device__ __forceinline__ void cp16(uint32_t dst, const void* src) {
    asm volatile("cp.async.cg.shared.global [%0], [%1], 16;"
                 :: "r"(dst), "l"(src) : "memory");
}
__device__ __forceinline__ void cp_commit() {
    asm volatile("cp.async.commit_group;" ::: "memory");
}
__device__ __forceinline__ void cp_wait1() {
    asm volatile("cp.async.wait_group 1;" ::: "memory");
}

__device__ __forceinline__ void ldsm_x4(uint32_t* r, uint32_t addr) {
    asm volatile("ldmatrix.sync.aligned.m8n8.x4.shared.b16 {%0,%1,%2,%3}, [%4];"
                 : "=r"(r[0]), "=r"(r[1]), "=r"(r[2]), "=r"(r[3]) : "r"(addr));
}

__device__ __forceinline__ void mma_f16(float* d, const uint32_t* a, uint32_t b0, uint32_t b1) {
    asm volatile(
        "mma.sync.aligned.m16n8k16.row.col.f32.f16.f16.f32 "
        "{%0,%1,%2,%3}, {%4,%5,%6,%7}, {%8,%9}, {%0,%1,%2,%3};"
        : "+f"(d[0]), "+f"(d[1]), "+f"(d[2]), "+f"(d[3])
        : "r"(a[0]), "r"(a[1]), "r"(a[2]), "r"(a[3]), "r"(b0), "r"(b1));
}

// ---- pre-pass converts: fp32 -> fp16 rn, 4 float4 per thread (MLP=4) ----
__global__ __launch_bounds__(256)
void convert_A_kernel(const float* __restrict__ src) {
    size_t base = (size_t)blockIdx.x * 1024 + threadIdx.x;
    #pragma unroll
    for (int k = 0; k < 4; k++) {
        size_t i = base + (size_t)k * 256;
        float4 v = reinterpret_cast<const float4*>(src)[i];
        uint2 h = make_uint2(pack2h(__float2half_rn(v.x), __float2half_rn(v.y)),
                             pack2h(__float2half_rn(v.z), __float2half_rn(v.w)));
        reinterpret_cast<uint2*>(g_Ah)[i] = h;
    }
}

__global__ __launch_bounds__(256)
void convert_B_kernel(const float* __restrict__ src) {
    size_t base = (size_t)blockIdx.x * 1024 + threadIdx.x;
    #pragma unroll
    for (int k = 0; k < 4; k++) {
        size_t i = base + (size_t)k * 256;
        float4 v = reinterpret_cast<const float4*>(src)[i];
        uint2 h = make_uint2(pack2h(__float2half_rn(v.x), __float2half_rn(v.y)),
                             pack2h(__float2half_rn(v.z), __float2half_rn(v.w)));
        reinterpret_cast<uint2*>(g_Bh)[i] = h;
    }
}

// ---- main GEMM ----
__global__ __launch_bounds__(THREADS, 2)
void moe_gemm_f16f_kernel(const float* __restrict__ bias,    // [E, D_OUT]
                          const int*   __restrict__ cnt,     // [E]
                          float*       __restrict__ out)     // [T, D_OUT]
{
    extern __shared__ char smem[];
    const uint32_t sbase = smem_u32_of(smem);

    const int tid = threadIdx.x;
    const int wid = tid >> 5;
    const int lid = tid & 31;

    const int nBase = blockIdx.x * BN;
    const int mBase = blockIdx.y * BM;

    int e = 0;
    {
        int acc = 0;
        #pragma unroll
        for (int i = 0; i < NUM_E; i++) {
            int c = cnt[i];
            if (mBase >= acc + c) { acc += c; e = i + 1; }
        }
    }

    const int warp_m = (wid >> 2) * 64;
    const int warp_n = (wid & 3) * 32;

    // ldmatrix lane addressing (verified rounds 3-14)
    const int a_row = (lid & 7) + ((lid >> 3) & 1) * 8;
    const int a_c2  = (lid >> 4) & 1;
    const int b_row = (lid & 7) + ((lid >> 4) & 1) * 8;
    const int b_c2  = (lid >> 3) & 1;

    // cp.async mapping: per chunk each tile is 128 rows x 128B = 1024 x16B,
    // 4 pieces per thread per tile. idx = o*256+tid: row = idx>>3, p = idx&7.
    const __half* aH = g_Ah + (size_t)mBase * D_IN;
    const __half* bH = g_Bh + (size_t)e * D_OUT * D_IN + (size_t)nBase * D_IN;

    uint32_t c_dst[4];
    int c_row[4], c_p[4];
    #pragma unroll
    for (int o = 0; o < 4; o++) {
        int idx = o * 256 + tid;
        c_row[o] = idx >> 3;
        c_p[o]   = idx & 7;
        c_dst[o] = (uint32_t)((c_p[o] >> 1) * REG_SZ) +
                   swz((uint32_t)(c_row[o] * 32 + (c_p[o] & 1) * 16));
    }

    float d[4][4][4];
    #pragma unroll
    for (int f = 0; f < 4; f++)
        #pragma unroll
        for (int n = 0; n < 4; n++)
            #pragma unroll
            for (int k = 0; k < 4; k++)
                d[f][n][k] = 0.0f;

    auto issue = [&](int chunk, int stage) {
        const uint32_t st = sbase + (uint32_t)stage * STAGE_B;
        const int kb = chunk * BK;
        #pragma unroll
        for (int o = 0; o < 4; o++)
            cp16(st + A_T + c_dst[o], aH + (size_t)c_row[o] * D_IN + kb + c_p[o] * 8);
        #pragma unroll
        for (int o = 0; o < 4; o++)
            cp16(st + B_T + c_dst[o], bH + (size_t)c_row[o] * D_IN + kb + c_p[o] * 8);
    };

    auto k16 = [&](uint32_t hb) {
        uint32_t bh[2][4];
        #pragma unroll
        for (int nb = 0; nb < 2; nb++) {
            uint32_t a = swz((uint32_t)((warp_n + nb * 16 + b_row) * 32 + b_c2 * 16));
            ldsm_x4(bh[nb], hb + B_T + a);
        }
        uint32_t af[4][4];
        #pragma unroll
        for (int f = 0; f < 4; f++) {
            uint32_t a = swz((uint32_t)((warp_m + f * 16 + a_row) * 32 + a_c2 * 16));
            ldsm_x4(af[f], hb + A_T + a);
        }
        #pragma unroll
        for (int f = 0; f < 4; f++)
            #pragma unroll
            for (int nb = 0; nb < 2; nb++) {
                mma_f16(d[f][nb * 2 + 0], af[f], bh[nb][0], bh[nb][1]);
                mma_f16(d[f][nb * 2 + 1], af[f], bh[nb][2], bh[nb][3]);
            }
    };

    // ---- prologue: stages 0,1 ----
    issue(0, 0); cp_commit();
    issue(1, 1); cp_commit();

    #pragma unroll 1
    for (int i = 0; i < NCHUNK; i++) {
        // sync guards: compute(i-1) finished before overwriting stage (i-1)%3
        __syncthreads();
        if (i + 2 < NCHUNK) issue(i + 2, (i + 2) % NSTAGE);
        cp_commit();
        cp_wait1();   // <=1 group pending => stage i%3 is filled

        const uint32_t cur = sbase + (uint32_t)(i % NSTAGE) * STAGE_B;
        k16(cur);
        k16(cur + REG_SZ);
        k16(cur + 2 * REG_SZ);
        k16(cur + 3 * REG_SZ);
    }

    // ---- epilogue: bias + fp32 store ----
    const int g  = lid >> 2;
    const int t4 = lid & 3;
    const float* brow = bias + (size_t)e * D_OUT;
    #pragma unroll
    for (int f = 0; f < 4; f++) {
        const int row0 = mBase + warp_m + f * 16 + g;
        #pragma unroll
        for (int nf = 0; nf < 4; nf++) {
            const int col = nBase + warp_n + nf * 8 + t4 * 2;
            float2 bv = *reinterpret_cast<const float2*>(brow + col);
            float2 o0, o1;
            o0.x = d[f][nf][0] + bv.x;
            o0.y = d[f][nf][1] + bv.y;
            o1.x = d[f][nf][2] + bv.x;
            o1.y = d[f][nf][3] + bv.y;
            *reinterpret_cast<float2*>(out + (size_t)row0 * D_OUT + col) = o0;
            *reinterpret_cast<float2*>(out + (size_t)(row0 + 8) * D_OUT + col) = o1;
        }
    }
}

extern "C" void kernel_launch(void* const* d_in, const int* in_sizes, int n_in,
                              void* d_out, int out_size)
{
    const float* inp    = (const float*)d_in[0];
    const float* weight = (const float*)d_in[1];
    const float* bias   = (const float*)d_in[2];
    const int*   cnt    = (const int*)d_in[3];
    float* out = (float*)d_out;

    // A: 4.19M float4 / 1024 per block = 4096 blocks
    convert_A_kernel<<<4096, 256>>>(inp);
    // B: 67.1M float4 / 1024 per block = 65536 blocks
    convert_B_kernel<<<65536, 256>>>(weight);

    cudaFuncSetAttribute(moe_gemm_f16f_kernel,
                         cudaFuncAttributeMaxDynamicSharedMemorySize, SMEM_BYTES);

    dim3 grid(D_OUT / BN, T_TOK / BM);   // (64, 64)
    moe_gemm_f16f_kernel<<<grid, THREADS, SMEM_BYTES>>>(bias, cnt, out);
}